// round 1
// baseline (speedup 1.0000x reference)
#include <cuda_runtime.h>
#include <cuda_bf16.h>

// Problem constants: B=4, C=256, H=W=64 -> HW=4096, vis=1024, scale=1.0
#define CDIM 256
#define HWDIM 4096
#define VIS 1024
#define BM 128
#define BN 128
#define KC 16

// S[b,q,k] = sum_c Q[b,c,q] * K[b,c,k]
// One CTA per (batch, 128-row q-strip); CTA sweeps all k so the argmax
// reduction stays CTA-local. 256 threads, 8x8 micro-tile per thread split as
// 2x(4 rows) x 2x(4 cols) halves for conflict-free float4 LDS.
__global__ __launch_bounds__(256, 1)
void attn_gemm_argmax(const float* __restrict__ Q,
                      const float* __restrict__ Km,
                      float* __restrict__ Svis,
                      void* __restrict__ Hout,
                      int hmode)
{
    const int b  = blockIdx.y;
    const int q0 = blockIdx.x * BM;
    const float* Qb = Q  + (size_t)b * CDIM * HWDIM;
    const float* Kb = Km + (size_t)b * CDIM * HWDIM;

    __shared__ float As[2][KC][BM];
    __shared__ float Bs[2][KC][BN];

    const int tid = threadIdx.x;
    const int tx = tid & 15;   // col group
    const int ty = tid >> 4;   // row group

    // Chunk loader: 16x128 floats = 512 float4, 2 per thread.
    const int f0 = tid, f1 = tid + 256;
    const int lc0 = f0 >> 5, lx0 = (f0 & 31) << 2;
    const int lc1 = f1 >> 5, lx1 = (f1 & 31) << 2;

    const float NEG_INF = __int_as_float(0xff800000);
    float run_v[8];
    int   run_i[8];
#pragma unroll
    for (int r = 0; r < 8; ++r) { run_v[r] = NEG_INF; run_i[r] = 0; }

    for (int nt = 0; nt < HWDIM / BN; ++nt) {
        const int n0 = nt * BN;

        float acc[2][4][2][4];
#pragma unroll
        for (int hr = 0; hr < 2; ++hr)
#pragma unroll
        for (int i = 0; i < 4; ++i)
#pragma unroll
        for (int hc = 0; hc < 2; ++hc)
#pragma unroll
        for (int j = 0; j < 4; ++j)
            acc[hr][i][hc][j] = 0.f;

        // Load K-chunk 0
        *(float4*)&As[0][lc0][lx0] = *(const float4*)&Qb[(size_t)lc0 * HWDIM + q0 + lx0];
        *(float4*)&As[0][lc1][lx1] = *(const float4*)&Qb[(size_t)lc1 * HWDIM + q0 + lx1];
        *(float4*)&Bs[0][lc0][lx0] = *(const float4*)&Kb[(size_t)lc0 * HWDIM + n0 + lx0];
        *(float4*)&Bs[0][lc1][lx1] = *(const float4*)&Kb[(size_t)lc1 * HWDIM + n0 + lx1];
        __syncthreads();

        for (int cc = 0; cc < CDIM / KC; ++cc) {
            const int cur = cc & 1;
            float4 pa0, pa1, pb0, pb1;
            const bool more = (cc + 1) < (CDIM / KC);
            if (more) {
                const int cb = (cc + 1) * KC;
                pa0 = *(const float4*)&Qb[(size_t)(cb + lc0) * HWDIM + q0 + lx0];
                pa1 = *(const float4*)&Qb[(size_t)(cb + lc1) * HWDIM + q0 + lx1];
                pb0 = *(const float4*)&Kb[(size_t)(cb + lc0) * HWDIM + n0 + lx0];
                pb1 = *(const float4*)&Kb[(size_t)(cb + lc1) * HWDIM + n0 + lx1];
            }
#pragma unroll
            for (int c = 0; c < KC; ++c) {
                float4 a0 = *(const float4*)&As[cur][c][ty * 4];
                float4 a1 = *(const float4*)&As[cur][c][64 + ty * 4];
                float4 b0 = *(const float4*)&Bs[cur][c][tx * 4];
                float4 b1 = *(const float4*)&Bs[cur][c][64 + tx * 4];
                float av[2][4] = {{a0.x, a0.y, a0.z, a0.w}, {a1.x, a1.y, a1.z, a1.w}};
                float bv[2][4] = {{b0.x, b0.y, b0.z, b0.w}, {b1.x, b1.y, b1.z, b1.w}};
#pragma unroll
                for (int hr = 0; hr < 2; ++hr)
#pragma unroll
                for (int i = 0; i < 4; ++i)
#pragma unroll
                for (int hc = 0; hc < 2; ++hc)
#pragma unroll
                for (int j = 0; j < 4; ++j)
                    acc[hr][i][hc][j] = fmaf(av[hr][i], bv[hc][j], acc[hr][i][hc][j]);
            }
            __syncthreads();
            if (more) {
                const int nxt = cur ^ 1;
                *(float4*)&As[nxt][lc0][lx0] = pa0;
                *(float4*)&As[nxt][lc1][lx1] = pa1;
                *(float4*)&Bs[nxt][lc0][lx0] = pb0;
                *(float4*)&Bs[nxt][lc1][lx1] = pb1;
                __syncthreads();
            }
        }

        // Per-thread running argmax update; k visited in ascending order so
        // strict > keeps the FIRST max index (matches jnp.argmax ties).
#pragma unroll
        for (int hr = 0; hr < 2; ++hr)
#pragma unroll
        for (int i = 0; i < 4; ++i) {
            const int r = hr * 4 + i;
#pragma unroll
            for (int hc = 0; hc < 2; ++hc)
#pragma unroll
            for (int j = 0; j < 4; ++j) {
                float v = acc[hr][i][hc][j];
                int k = n0 + hc * 64 + tx * 4 + j;
                if (v > run_v[r]) { run_v[r] = v; run_i[r] = k; }
            }
        }

        // Visible-corner store (whole 128x128 tiles are either in or out).
        if (q0 < VIS && n0 < VIS) {
#pragma unroll
            for (int hr = 0; hr < 2; ++hr)
#pragma unroll
            for (int i = 0; i < 4; ++i) {
                const int q = q0 + hr * 64 + ty * 4 + i;
                float* row = Svis + (size_t)b * VIS * VIS + (size_t)q * VIS + n0;
                float4 v0 = make_float4(acc[hr][i][0][0], acc[hr][i][0][1],
                                        acc[hr][i][0][2], acc[hr][i][0][3]);
                float4 v1 = make_float4(acc[hr][i][1][0], acc[hr][i][1][1],
                                        acc[hr][i][1][2], acc[hr][i][1][3]);
                *(float4*)&row[tx * 4]      = v0;
                *(float4*)&row[64 + tx * 4] = v1;
            }
        }
    }

    // Cross-lane (16 lanes share a row group) argmax reduction; tie -> lower k.
#pragma unroll
    for (int r = 0; r < 8; ++r) {
        float v = run_v[r];
        int idx = run_i[r];
#pragma unroll
        for (int off = 8; off > 0; off >>= 1) {
            float ov = __shfl_xor_sync(0xffffffffu, v,   off, 16);
            int   oi = __shfl_xor_sync(0xffffffffu, idx, off, 16);
            if (ov > v || (ov == v && oi < idx)) { v = ov; idx = oi; }
        }
        if (tx == 0) {
            const int q = q0 + (r >> 2) * 64 + ty * 4 + (r & 3);
            if (hmode == 1) {
                ((long long*)Hout)[(size_t)b * HWDIM + q] = (long long)idx;
            } else {
                ((float*)Hout)[(size_t)b * HWDIM + q] = (float)idx;
            }
        }
    }
}

extern "C" void kernel_launch(void* const* d_in, const int* in_sizes, int n_in,
                              void* d_out, int out_size)
{
    const float* Q = (const float*)d_in[0];
    const float* K = (const float*)d_in[1];
    // V (d_in[2]) is unused by the reference outputs.

    float* Svis = (float*)d_out;
    const size_t svis_elems = (size_t)4 * VIS * VIS;  // 4,194,304

    // Output packing hedge:
    //  - out_size == 4,227,072 fp32-slots: S_vis fp32 then raw int64 H_idx.
    //  - otherwise (4,210,688): everything as fp32 (idx values exact in fp32).
    int hmode;
    void* hptr;
    if (out_size == 4227072) {
        hmode = 1;
        hptr = (void*)((char*)d_out + svis_elems * sizeof(float));
    } else {
        hmode = 0;
        hptr = (void*)((float*)d_out + svis_elems);
    }

    dim3 grid(HWDIM / BM, 4);  // 32 q-strips x 4 batches = 128 CTAs
    attn_gemm_argmax<<<grid, 256>>>(Q, K, Svis, hptr, hmode);
}

// round 4
// speedup vs baseline: 2.1078x; 2.1078x over previous
#include <cuda_runtime.h>
#include <cuda_fp16.h>
#include <cstdint>

// Problem: B=4, C=256, HW=4096. S = Q^T K per batch; outputs S[:, :1024, :1024] + argmax rows.
#define BATCH   4
#define CDIM    256
#define HWDIM   4096
#define VIS     1024
#define KSPLIT  512            // [hi(256) | lo(256)] halfs per hw-row
#define TILE_M  128
#define TILE_N  128
#define NCHUNKS (HWDIM / TILE_N)        // 32
#define KSTEPS  24                      // per chunk: K_eff=768 in BK=32 steps
#define TOTSTEPS (NCHUNKS * KSTEPS)     // 768
#define STAGE_BYTES 16384               // A 8KB + B 8KB
#define SM_RED  65536                   // after 4 stages
#define SM_TOTAL (SM_RED + 4096)

// Scratch: transposed + fp16 hi/lo split operands (allocation-free device globals).
__device__ __half g_QT[(size_t)BATCH * HWDIM * KSPLIT];
__device__ __half g_KT[(size_t)BATCH * HWDIM * KSPLIT];

#define CP16(dst, src) \
    asm volatile("cp.async.cg.shared.global [%0], [%1], 16;" :: "r"(dst), "l"(src))
#define CP_COMMIT() asm volatile("cp.async.commit_group;" ::: "memory")
#define CP_WAIT2()  asm volatile("cp.async.wait_group 2;" ::: "memory")

__device__ __forceinline__ uint32_t smem_u32(const void* p) {
    uint32_t a;
    asm("{ .reg .u64 t; cvta.to.shared.u64 t, %1; cvt.u32.u64 %0, t; }" : "=r"(a) : "l"(p));
    return a;
}
__device__ __forceinline__ void ldsm4(uint32_t* r, uint32_t addr) {
    asm volatile("ldmatrix.sync.aligned.m8n8.x4.shared.b16 {%0,%1,%2,%3}, [%4];"
                 : "=r"(r[0]), "=r"(r[1]), "=r"(r[2]), "=r"(r[3]) : "r"(addr));
}
__device__ __forceinline__ void mma16816(float* d, const uint32_t* a, const uint32_t* b) {
    asm volatile("mma.sync.aligned.m16n8k16.row.col.f32.f16.f16.f32 "
                 "{%0,%1,%2,%3}, {%4,%5,%6,%7}, {%8,%9}, {%0,%1,%2,%3};"
                 : "+f"(d[0]), "+f"(d[1]), "+f"(d[2]), "+f"(d[3])
                 : "r"(a[0]), "r"(a[1]), "r"(a[2]), "r"(a[3]), "r"(b[0]), "r"(b[1]));
}

// ---- Kernel 1: transpose + fp16 hi/lo split ----
// src[b][c][hw] fp32 -> dst[b][hw][c]=hi, dst[b][hw][256+c]=lo
__global__ __launch_bounds__(256, 4)
void split_tp(const float* __restrict__ Q, const float* __restrict__ K)
{
    const int bz = blockIdx.z;                   // bit0 = which tensor, bits1.. = batch
    const float* src = ((bz & 1) ? K : Q) + (size_t)(bz >> 1) * CDIM * HWDIM;
    __half* dst = ((bz & 1) ? g_KT : g_QT) + (size_t)(bz >> 1) * HWDIM * KSPLIT;
    __shared__ float t[32][33];
    const int x0 = blockIdx.x * 32;              // hw
    const int y0 = blockIdx.y * 32;              // c
    const int tx = threadIdx.x & 31, ty = threadIdx.x >> 5;
#pragma unroll
    for (int j = 0; j < 4; ++j)
        t[ty + 8 * j][tx] = src[(size_t)(y0 + ty + 8 * j) * HWDIM + x0 + tx];
    __syncthreads();
#pragma unroll
    for (int j = 0; j < 4; ++j) {
        const int hw = x0 + ty + 8 * j;
        const float x = t[tx][ty + 8 * j];
        const __half hi = __float2half_rn(x);
        const __half lo = __float2half_rn(x - __half2float(hi));
        const size_t o = (size_t)hw * KSPLIT + y0 + tx;
        dst[o] = hi;
        dst[o + CDIM] = lo;
    }
}

// issue one cp.async stage: A tile 128x32 halfs, B tile 128x32 halfs, swizzled.
__device__ __forceinline__ void issue_stage(
    uint32_t smb, int slot, const __half* QTb, const __half* KTb,
    int chunk, int ks, int soff /* r0*512+u0*8 */, int dst0 /* swizzled byte off */)
{
    const int seg = ks >> 3, kb = ks & 7;
    const int ca = ((seg == 2) ? CDIM : 0) + kb * 32;   // A: [hi | hi | lo]
    const int cb = ((seg == 1) ? CDIM : 0) + kb * 32;   // B: [hi | lo | hi]
    const uint32_t ab = smb + slot * STAGE_BYTES;
    const uint32_t bb = ab + 8192;
    const __half* pa = QTb + soff + ca;
    CP16(ab + dst0, pa);
    CP16(ab + dst0 + 4096, pa + 64 * KSPLIT);
    const __half* pb = KTb + (size_t)chunk * TILE_N * KSPLIT + soff + cb;
    CP16(bb + dst0, pb);
    CP16(bb + dst0 + 4096, pb + 64 * KSPLIT);
}

// ---- Kernel 2: fp16-split mma.sync GEMM + argmax + visible store ----
__global__ __launch_bounds__(256, 1)
void gemm_fp16(float* __restrict__ Svis, void* __restrict__ Hout, int hmode)
{
    extern __shared__ char smem[];
    const uint32_t smb = smem_u32(smem);
    const int tid = threadIdx.x;
    const int lane = tid & 31, wid = tid >> 5;
    const int wm = wid >> 2, wn = wid & 3;          // warp grid 2(M) x 4(N)
    const int b = blockIdx.y;
    const int q0 = blockIdx.x * TILE_M;

    const __half* QTb = g_QT + ((size_t)(b * HWDIM + q0)) * KSPLIT;
    const __half* KTb = g_KT + (size_t)b * HWDIM * KSPLIT;

    // cp.async mapping: thread covers unit i=tid and i=tid+256 of 512 16B-units.
    const int r0 = tid >> 2, u0 = tid & 3;
    const int soff = r0 * KSPLIT + u0 * 8;
    const int dst0 = r0 * 64 + ((u0 ^ ((r0 >> 1) & 3)) * 16);

    // ldmatrix lane geometry
    const int arow = lane & 15;                 // A x4: rows from lane bits 0-3
    const int auk  = (lane >> 4) & 1;           // A: 16B half of k16 from bit 4
    const int brow = (lane & 7) + ((lane >> 4) & 1) * 8;  // B x4 rows
    const int buk  = (lane >> 3) & 1;           // B: 16B half from bit 3

    int am[4], axor[4];
#pragma unroll
    for (int mt = 0; mt < 4; ++mt) {
        const int m = wm * 64 + mt * 16 + arow;
        am[mt] = m * 64;
        axor[mt] = (m >> 1) & 3;
    }
    int bn[2], bxor[2];
#pragma unroll
    for (int p = 0; p < 2; ++p) {
        const int n = wn * 32 + p * 16 + brow;
        bn[p] = n * 64;
        bxor[p] = (n >> 1) & 3;
    }

    const float NEG_INF = __int_as_float(0xff800000);
    float run_v[8];
    int   run_i[8];
#pragma unroll
    for (int s = 0; s < 8; ++s) { run_v[s] = NEG_INF; run_i[s] = 0; }

    // Prologue: 3 stages in flight
    int pf_chunk = 0, pf_ks = 0;
#pragma unroll
    for (int s = 0; s < 3; ++s) {
        issue_stage(smb, s, QTb, KTb, pf_chunk, pf_ks, soff, dst0);
        CP_COMMIT();
        if (++pf_ks == KSTEPS) { pf_ks = 0; ++pf_chunk; }
    }

    int gs = 0;
    const bool visq = (q0 < VIS);

    for (int chunk = 0; chunk < NCHUNKS; ++chunk) {
        float acc[4][4][4];
#pragma unroll
        for (int mt = 0; mt < 4; ++mt)
#pragma unroll
        for (int nt = 0; nt < 4; ++nt)
#pragma unroll
        for (int e = 0; e < 4; ++e) acc[mt][nt][e] = 0.f;

        for (int ks = 0; ks < KSTEPS; ++ks, ++gs) {
            CP_WAIT2();
            __syncthreads();
            const int slot = gs & 3;
            const uint32_t ab = smb + slot * STAGE_BYTES;
            const uint32_t bb = ab + 8192;
#pragma unroll
            for (int k16 = 0; k16 < 2; ++k16) {
                uint32_t af[4][4];
#pragma unroll
                for (int mt = 0; mt < 4; ++mt) {
                    const int u = (k16 * 2 + auk) ^ axor[mt];
                    ldsm4(af[mt], ab + am[mt] + u * 16);
                }
                uint32_t bf[2][4];
#pragma unroll
                for (int p = 0; p < 2; ++p) {
                    const int u = (k16 * 2 + buk) ^ bxor[p];
                    ldsm4(bf[p], bb + bn[p] + u * 16);
                }
#pragma unroll
                for (int mt = 0; mt < 4; ++mt)
#pragma unroll
                for (int nt = 0; nt < 4; ++nt)
                    mma16816(acc[mt][nt], af[mt], &bf[nt >> 1][(nt & 1) * 2]);
            }
            if (gs + 3 < TOTSTEPS) {
                issue_stage(smb, (gs + 3) & 3, QTb, KTb, pf_chunk, pf_ks, soff, dst0);
                if (++pf_ks == KSTEPS) { pf_ks = 0; ++pf_chunk; }
            }
            CP_COMMIT();
        }

        // Epilogue: argmax update + visible-corner store, straight from fragments.
        const int n0 = chunk * TILE_N;
#pragma unroll
        for (int mt = 0; mt < 4; ++mt)
#pragma unroll
        for (int nt = 0; nt < 4; ++nt) {
            const int nb = n0 + wn * 32 + nt * 8 + (lane & 3) * 2;
#pragma unroll
            for (int h = 0; h < 2; ++h) {
                const int s = mt * 2 + h;
#pragma unroll
                for (int j = 0; j < 2; ++j) {
                    const float v = acc[mt][nt][h * 2 + j];
                    if (v > run_v[s]) { run_v[s] = v; run_i[s] = nb + j; }
                }
            }
        }
        if (visq && n0 < VIS) {
#pragma unroll
            for (int mt = 0; mt < 4; ++mt)
#pragma unroll
            for (int h = 0; h < 2; ++h) {
                const int q = q0 + wm * 64 + mt * 16 + (lane >> 2) + h * 8;
                float* row = Svis + ((size_t)(b * VIS + q)) * VIS;
#pragma unroll
                for (int nt = 0; nt < 4; ++nt) {
                    const int n = n0 + wn * 32 + nt * 8 + (lane & 3) * 2;
                    float2 v2 = make_float2(acc[mt][nt][h * 2], acc[mt][nt][h * 2 + 1]);
                    *(float2*)(row + n) = v2;
                }
            }
        }
    }

    // Reduce argmax: lanes sharing a row differ only in bits 0-1 of lane.
#pragma unroll
    for (int s = 0; s < 8; ++s) {
        float v = run_v[s];
        int idx = run_i[s];
#pragma unroll
        for (int off = 1; off <= 2; off <<= 1) {
            float ov = __shfl_xor_sync(0xffffffffu, v, off);
            int   oi = __shfl_xor_sync(0xffffffffu, idx, off);
            if (ov > v || (ov == v && oi < idx)) { v = ov; idx = oi; }
        }
        run_v[s] = v; run_i[s] = idx;
    }
    float* mv = (float*)(smem + SM_RED);
    int*   mi = (int*)(smem + SM_RED + 2048);
    __syncthreads();
    if ((lane & 3) == 0) {
#pragma unroll
        for (int s = 0; s < 8; ++s) {
            const int mt = s >> 1, h = s & 1;
            const int row = wm * 64 + mt * 16 + (lane >> 2) + h * 8;
            mv[wn * 128 + row] = run_v[s];
            mi[wn * 128 + row] = run_i[s];
        }
    }
    __syncthreads();
    if (tid < 128) {
        float v = mv[tid];
        int idx = mi[tid];
#pragma unroll
        for (int w = 1; w < 4; ++w) {
            const float ov = mv[w * 128 + tid];
            const int   oi = mi[w * 128 + tid];
            if (ov > v || (ov == v && oi < idx)) { v = ov; idx = oi; }
        }
        const size_t hq = (size_t)b * HWDIM + q0 + tid;
        if (hmode == 1) ((long long*)Hout)[hq] = (long long)idx;
        else            ((float*)Hout)[hq] = (float)idx;
    }
}

extern "C" void kernel_launch(void* const* d_in, const int* in_sizes, int n_in,
                              void* d_out, int out_size)
{
    const float* Q = (const float*)d_in[0];
    const float* K = (const float*)d_in[1];
    // V unused by reference outputs.

    float* Svis = (float*)d_out;
    const size_t svis_elems = (size_t)BATCH * VIS * VIS;

    int hmode;
    void* hptr;
    if (out_size == 4227072) {
        hmode = 1;
        hptr = (void*)((char*)d_out + svis_elems * sizeof(float));
    } else {
        hmode = 0;
        hptr = (void*)((float*)d_out + svis_elems);
    }

    static int attr_done = 0;
    if (!attr_done) {
        cudaFuncSetAttribute(gemm_fp16, cudaFuncAttributeMaxDynamicSharedMemorySize, SM_TOTAL);
        attr_done = 1;
    }

    split_tp<<<dim3(HWDIM / 32, CDIM / 32, 2 * BATCH), 256>>>(Q, K);
    gemm_fp16<<<dim3(HWDIM / TILE_M, BATCH), 256, SM_TOTAL>>>(Svis, hptr, hmode);
}